// round 11
// baseline (speedup 1.0000x reference)
#include <cuda_runtime.h>
#include <cuda_fp16.h>
#include <cstdint>

#define S_TOK 8192
#define MDIM  2048
#define EEXP  8
#define HDIM  8192
#define CAP   2048

// ----------------- static device scratch -----------------------------------
__device__ int   g_idx[S_TOK];
__device__ float g_gw[S_TOK];
__device__ int   g_tfs[EEXP * CAP];
__device__ int   g_rows[EEXP];
__device__ __align__(128) __half g_x_hi[(size_t)S_TOK * MDIM];
__device__ __align__(128) __half g_h_hi[(size_t)EEXP * CAP * HDIM];
__device__ __align__(128) __half g_w1t_hi[(size_t)EEXP * HDIM * MDIM];   // [N=H][K=M]
__device__ __align__(128) __half g_w2t_hi[(size_t)EEXP * MDIM * HDIM];   // [N=M][K=H]

// ----------------- small helpers -------------------------------------------
__device__ __forceinline__ uint32_t smem_u32(const void* p) {
    uint32_t a;
    asm("{ .reg .u64 t; cvta.to.shared.u64 t, %1; cvt.u32.u64 %0, t; }" : "=r"(a) : "l"(p));
    return a;
}
__device__ __forceinline__ uint32_t SWZ(uint32_t o) { return o ^ ((o >> 3) & 0x70u); }

__device__ __forceinline__ uint32_t packh(float f0, float f1) {
    uint32_t r;
    asm("cvt.rn.f16x2.f32 %0, %1, %2;" : "=r"(r) : "f"(f1), "f"(f0));
    return r;
}
__device__ __forceinline__ void cpa(uint32_t d, const void* s) {
    asm volatile("cp.async.cg.shared.global [%0], [%1], 16;" :: "r"(d), "l"(s) : "memory");
}
__device__ __forceinline__ void ldsm4(uint32_t* r, uint32_t a) {
    asm volatile("ldmatrix.sync.aligned.m8n8.x4.shared.b16 {%0,%1,%2,%3}, [%4];"
                 : "=r"(r[0]), "=r"(r[1]), "=r"(r[2]), "=r"(r[3]) : "r"(a));
}
__device__ __forceinline__ void mmah(float* c, const uint32_t* a, uint32_t b0, uint32_t b1) {
    asm volatile("mma.sync.aligned.m16n8k16.row.col.f32.f16.f16.f32 "
                 "{%0,%1,%2,%3}, {%4,%5,%6,%7}, {%8,%9}, {%0,%1,%2,%3};"
                 : "+f"(c[0]), "+f"(c[1]), "+f"(c[2]), "+f"(c[3])
                 : "r"(a[0]), "r"(a[1]), "r"(a[2]), "r"(a[3]), "r"(b0), "r"(b1));
}
__device__ __forceinline__ float gelu_tanh(float v) {
    float t = tanhf(0.7978845608028654f * (v + 0.044715f * v * v * v));
    return 0.5f * v * (1.f + t);
}

// ----------------- gate + x fp16 convert ------------------------------------
__global__ void gate_kernel(const float* __restrict__ x, const float* __restrict__ Wg) {
    int s = blockIdx.x;
    int w = threadIdx.x >> 5, lane = threadIdx.x & 31;
    const float* xr = x + (size_t)s * MDIM;
    float sum = 0.f;
    for (int m = lane; m < MDIM; m += 32)
        sum += xr[m] * Wg[m * EEXP + w];
    #pragma unroll
    for (int o = 16; o; o >>= 1) sum += __shfl_xor_sync(0xffffffffu, sum, o);
    __shared__ float lg[EEXP];
    if (lane == 0) lg[w] = sum;
    // convert this token's row to fp16 while it is hot in L1
    const float2* xr2 = (const float2*)xr;
    uint32_t* dst = (uint32_t*)(g_x_hi + (size_t)s * MDIM);
    #pragma unroll
    for (int j = 0; j < MDIM / 2 / 256; j++) {
        int idx = threadIdx.x + j * 256;
        float2 v = xr2[idx];
        dst[idx] = packh(v.x, v.y);
    }
    __syncthreads();
    if (threadIdx.x == 0) {
        float mx = lg[0]; int mi = 0;
        #pragma unroll
        for (int e = 1; e < EEXP; e++) if (lg[e] > mx) { mx = lg[e]; mi = e; }
        float se = 0.f;
        #pragma unroll
        for (int e = 0; e < EEXP; e++) se += expf(lg[e] - mx);
        g_idx[s] = mi;
        g_gw[s]  = 1.f / se;
    }
}

// ----------------- routing -------------------------------------------------
__global__ void route_kernel() {
    int lane = threadIdx.x;
    int cnt = 0;
    for (int s0 = 0; s0 < S_TOK; s0 += 32) {
        int s  = s0 + lane;
        int id = g_idx[s];
        int pos = 0;
        #pragma unroll
        for (int e = 0; e < EEXP; e++) {
            unsigned b = __ballot_sync(0xffffffffu, id == e);
            int base   = __shfl_sync(0xffffffffu, cnt, e);
            if (id == e)   pos = base + __popc(b & ((1u << lane) - 1u));
            if (lane == e) cnt += __popc(b);
        }
        if (pos < CAP) g_tfs[id * CAP + pos] = s;
        else           g_gw[s] = 0.f;
    }
    if (lane < EEXP) g_rows[lane] = min(cnt, CAP);
}

// ----------------- weight transpose (fp16, 64x64 tiles, wide writes) --------
template<bool W1SEL>
__global__ __launch_bounds__(256)
void transpose_split(const float* __restrict__ src) {
    constexpr int R  = W1SEL ? MDIM : HDIM;   // src rows (= out cols = K)
    constexpr int Cc = W1SEL ? HDIM : MDIM;   // src cols (= out rows = N)
    __half* dhi = W1SEL ? g_w1t_hi : g_w2t_hi;
    __shared__ float t[64][65];
    int e = blockIdx.z;
    const float* s = src + (size_t)e * R * Cc;
    size_t ob = (size_t)e * R * Cc;
    int c0 = blockIdx.x * 64, r0 = blockIdx.y * 64;
    int tid = threadIdx.x;
    int rr = tid >> 6, cc = tid & 63;
    #pragma unroll
    for (int i = 0; i < 16; i++) {
        int r = i * 4 + rr;
        t[r][cc] = s[(size_t)(r0 + r) * Cc + c0 + cc];
    }
    __syncthreads();
    int orr = tid >> 5, j = tid & 31;
    #pragma unroll
    for (int i = 0; i < 8; i++) {
        int oc = orr + i * 8;   // src-col index within tile (= out row offset)
        __half2 v = __floats2half2_rn(t[2 * j][oc], t[2 * j + 1][oc]);
        *(__half2*)(dhi + ob + (size_t)(c0 + oc) * R + r0 + 2 * j) = v;
    }
}

// ----------------- HMMA fp16 GEMM (BM=BN=128, 3 stages, 2 CTA/SM) -----------
#define BM 128
#define BN 128
#define BK 64
#define OFF_AHI 0
#define OFF_BHI 16384
#define STG 32768
#define SMEM_BYTES (3 * STG + 1024)

template<bool G1>
__global__ __launch_bounds__(256, 2)
void hgemm(float* __restrict__ outp) {
    constexpr int KD  = G1 ? MDIM : HDIM;
    constexpr int NT  = G1 ? HDIM : MDIM;
    constexpr int KCH = KD / BK;

    int e = blockIdx.z;
    int rows = g_rows[e];
    int rowBase = blockIdx.y * BM;
    if (rowBase >= rows) return;
    int colBase = blockIdx.x * BN;

    extern __shared__ char dsm[];
    uint32_t base = (smem_u32(dsm) + 1023u) & ~1023u;

    int t = threadIdx.x;

    // ---- loader setup: thread t loads 64B half of row (t>>1) ----
    int lr = t >> 1, half = t & 1;
    const __half* aHi;
    if (G1) {
        int rr = rowBase + lr;
        if (rr >= rows) rr = rows - 1;
        int tok = g_tfs[e * CAP + rr];
        aHi = g_x_hi + (size_t)tok * MDIM + half * 32;
    } else {
        aHi = g_h_hi + ((size_t)e * CAP + rowBase + lr) * HDIM + half * 32;
    }
    size_t bo0 = ((size_t)e * NT + colBase + lr) * KD + half * 32;
    const __half* bHi = G1 ? g_w1t_hi : g_w2t_hi;

    uint32_t d0[4];
    #pragma unroll
    for (int i = 0; i < 4; i++)
        d0[i] = SWZ(lr * 128 + (half * 4 + i) * 16);

    auto loadStage = [&](int s, int kt) {
        uint32_t sb = base + s * STG;
        int ko = kt * BK;
        #pragma unroll
        for (int i = 0; i < 4; i++) {
            cpa(sb + OFF_AHI + d0[i], aHi + ko + i * 8);
            cpa(sb + OFF_BHI + d0[i], bHi + bo0 + ko + i * 8);
        }
    };

    // ---- compute setup: 8 warps as 4(m) x 2(n); warp tile 32 x 64 ----
    int wid = t >> 5, lane = t & 31;
    int m0 = (wid >> 1) * 32, n0 = (wid & 1) * 64;
    uint32_t aOff[2];
    #pragma unroll
    for (int mt = 0; mt < 2; mt++)
        aOff[mt] = (m0 + mt * 16 + (lane & 15)) * 128 + ((lane >> 4) * 16);
    uint32_t bOff = (n0 + (lane & 7) + ((lane >> 4) << 3)) * 128 + (((lane >> 3) & 1) * 16);

    float acc[64];
    #pragma unroll
    for (int i = 0; i < 64; i++) acc[i] = 0.f;

    loadStage(0, 0); asm volatile("cp.async.commit_group;" ::: "memory");
    loadStage(1, 1); asm volatile("cp.async.commit_group;" ::: "memory");

    int sIdx = 0;
    for (int kt = 0; kt < KCH; kt++) {
        asm volatile("cp.async.wait_group 1;" ::: "memory");
        __syncthreads();
        if (kt + 2 < KCH) {
            int ns = sIdx + 2; if (ns >= 3) ns -= 3;
            loadStage(ns, kt + 2);
        }
        asm volatile("cp.async.commit_group;" ::: "memory");

        uint32_t sb = base + sIdx * STG;
        #pragma unroll
        for (int ks = 0; ks < 4; ks++) {
            uint32_t ah[2][4];
            #pragma unroll
            for (int mt = 0; mt < 2; mt++)
                ldsm4(ah[mt], sb + OFF_AHI + SWZ(aOff[mt] + ks * 32));
            #pragma unroll
            for (int p = 0; p < 4; p++) {
                uint32_t bh[4];
                ldsm4(bh, sb + OFF_BHI + SWZ(bOff + p * 2048 + ks * 32));
                #pragma unroll
                for (int mt = 0; mt < 2; mt++) {
                    float* c0 = &acc[(mt * 8 + 2 * p) * 4];
                    float* c1 = &acc[(mt * 8 + 2 * p + 1) * 4];
                    mmah(c0, ah[mt], bh[0], bh[1]);
                    mmah(c1, ah[mt], bh[2], bh[3]);
                }
            }
        }
        if (++sIdx == 3) sIdx = 0;
    }

    // ---- epilogue ----
    int rq = lane >> 2, cq = (lane & 3) * 2;
    #pragma unroll
    for (int mt = 0; mt < 2; mt++) {
        #pragma unroll
        for (int h = 0; h < 2; h++) {
            int r = rowBase + m0 + mt * 16 + rq + h * 8;
            if (r < rows) {
                if (G1) {
                    size_t ro = ((size_t)e * CAP + r) * HDIM + colBase + n0 + cq;
                    #pragma unroll
                    for (int nt = 0; nt < 8; nt++) {
                        float v0 = gelu_tanh(acc[(mt * 8 + nt) * 4 + h * 2]);
                        float v1 = gelu_tanh(acc[(mt * 8 + nt) * 4 + h * 2 + 1]);
                        *(uint32_t*)(g_h_hi + ro + nt * 8) = packh(v0, v1);
                    }
                } else {
                    int tok = g_tfs[e * CAP + r];
                    float gw = g_gw[tok];
                    float* dst = outp + (size_t)tok * MDIM + colBase + n0 + cq;
                    #pragma unroll
                    for (int nt = 0; nt < 8; nt++) {
                        float2 v;
                        v.x = acc[(mt * 8 + nt) * 4 + h * 2]     * gw;
                        v.y = acc[(mt * 8 + nt) * 4 + h * 2 + 1] * gw;
                        *(float2*)(dst + nt * 8) = v;
                    }
                }
            }
        }
    }
}

// ----------------- launch ---------------------------------------------------
extern "C" void kernel_launch(void* const* d_in, const int* in_sizes, int n_in,
                              void* d_out, int out_size) {
    const float* x  = (const float*)d_in[0];
    const float* Wg = (const float*)d_in[1];
    const float* W1 = (const float*)d_in[2];
    const float* W2 = (const float*)d_in[3];
    float* out = (float*)d_out;

    static cudaStream_t s2 = nullptr, s3 = nullptr;
    static cudaEvent_t evRoot = nullptr, evW1 = nullptr, evW2 = nullptr;
    if (s2 == nullptr) {
        cudaStreamCreateWithFlags(&s2, cudaStreamNonBlocking);
        cudaStreamCreateWithFlags(&s3, cudaStreamNonBlocking);
        cudaEventCreateWithFlags(&evRoot, cudaEventDisableTiming);
        cudaEventCreateWithFlags(&evW1,   cudaEventDisableTiming);
        cudaEventCreateWithFlags(&evW2,   cudaEventDisableTiming);
        cudaFuncSetAttribute(hgemm<true>,  cudaFuncAttributeMaxDynamicSharedMemorySize, SMEM_BYTES);
        cudaFuncSetAttribute(hgemm<false>, cudaFuncAttributeMaxDynamicSharedMemorySize, SMEM_BYTES);
    }

    // fork two aux branches off the main (captured) stream
    cudaEventRecord(evRoot, 0);
    cudaStreamWaitEvent(s2, evRoot, 0);
    cudaStreamWaitEvent(s3, evRoot, 0);

    // branch s2: W1 transpose (overlaps gate+route on main)
    transpose_split<true ><<<dim3(HDIM / 64, MDIM / 64, EEXP), 256, 0, s2>>>(W1);
    cudaEventRecord(evW1, s2);

    // branch s3: W2 transpose + output clear (overlaps gate/route AND GEMM1)
    transpose_split<false><<<dim3(MDIM / 64, HDIM / 64, EEXP), 256, 0, s3>>>(W2);
    cudaMemsetAsync(d_out, 0, (size_t)S_TOK * MDIM * sizeof(float), s3);
    cudaEventRecord(evW2, s3);

    // main: gate -> route -> (join W1) -> GEMM1 -> (join W2/memset) -> GEMM2
    gate_kernel<<<S_TOK, 256>>>(x, Wg);
    route_kernel<<<1, 32>>>();
    cudaStreamWaitEvent(0, evW1, 0);
    hgemm<true ><<<dim3(HDIM / BN, CAP / BM, EEXP), 256, SMEM_BYTES>>>(nullptr);
    cudaStreamWaitEvent(0, evW2, 0);
    hgemm<false><<<dim3(MDIM / BN, CAP / BM, EEXP), 256, SMEM_BYTES>>>(out);
}

// round 12
// speedup vs baseline: 1.0604x; 1.0604x over previous
#include <cuda_runtime.h>
#include <cuda_fp16.h>
#include <cstdint>

#define S_TOK 8192
#define MDIM  2048
#define EEXP  8
#define HDIM  8192
#define CAP   2048

// ----------------- static device scratch -----------------------------------
__device__ int   g_idx[S_TOK];
__device__ float g_gw[S_TOK];
__device__ int   g_tfs[EEXP * CAP];
__device__ int   g_rows[EEXP];
__device__ __align__(128) __half g_x_hi[(size_t)S_TOK * MDIM];
__device__ __align__(128) __half g_h_hi[(size_t)EEXP * CAP * HDIM];
__device__ __align__(128) __half g_w1t_hi[(size_t)EEXP * HDIM * MDIM];   // [N=H][K=M]
__device__ __align__(128) __half g_w2t_hi[(size_t)EEXP * MDIM * HDIM];   // [N=M][K=H]

// ----------------- small helpers -------------------------------------------
__device__ __forceinline__ uint32_t smem_u32(const void* p) {
    uint32_t a;
    asm("{ .reg .u64 t; cvta.to.shared.u64 t, %1; cvt.u32.u64 %0, t; }" : "=r"(a) : "l"(p));
    return a;
}
__device__ __forceinline__ uint32_t SWZ(uint32_t o) { return o ^ ((o >> 3) & 0x70u); }

__device__ __forceinline__ uint32_t packh(float f0, float f1) {
    uint32_t r;
    asm("cvt.rn.f16x2.f32 %0, %1, %2;" : "=r"(r) : "f"(f1), "f"(f0));
    return r;
}
__device__ __forceinline__ void cpa(uint32_t d, const void* s) {
    asm volatile("cp.async.cg.shared.global [%0], [%1], 16;" :: "r"(d), "l"(s) : "memory");
}
__device__ __forceinline__ void ldsm4(uint32_t* r, uint32_t a) {
    asm volatile("ldmatrix.sync.aligned.m8n8.x4.shared.b16 {%0,%1,%2,%3}, [%4];"
                 : "=r"(r[0]), "=r"(r[1]), "=r"(r[2]), "=r"(r[3]) : "r"(a));
}
__device__ __forceinline__ void mmah(float* c, const uint32_t* a, uint32_t b0, uint32_t b1) {
    asm volatile("mma.sync.aligned.m16n8k16.row.col.f32.f16.f16.f32 "
                 "{%0,%1,%2,%3}, {%4,%5,%6,%7}, {%8,%9}, {%0,%1,%2,%3};"
                 : "+f"(c[0]), "+f"(c[1]), "+f"(c[2]), "+f"(c[3])
                 : "r"(a[0]), "r"(a[1]), "r"(a[2]), "r"(a[3]), "r"(b0), "r"(b1));
}
__device__ __forceinline__ float gelu_tanh(float v) {
    float t = tanhf(0.7978845608028654f * (v + 0.044715f * v * v * v));
    return 0.5f * v * (1.f + t);
}

// ----------------- gate + x fp16 convert ------------------------------------
__global__ void gate_kernel(const float* __restrict__ x, const float* __restrict__ Wg) {
    int s = blockIdx.x;
    int w = threadIdx.x >> 5, lane = threadIdx.x & 31;
    const float* xr = x + (size_t)s * MDIM;
    float sum = 0.f;
    for (int m = lane; m < MDIM; m += 32)
        sum += xr[m] * Wg[m * EEXP + w];
    #pragma unroll
    for (int o = 16; o; o >>= 1) sum += __shfl_xor_sync(0xffffffffu, sum, o);
    __shared__ float lg[EEXP];
    if (lane == 0) lg[w] = sum;
    // convert this token's row to fp16 while it is hot in L1
    const float2* xr2 = (const float2*)xr;
    uint32_t* dst = (uint32_t*)(g_x_hi + (size_t)s * MDIM);
    #pragma unroll
    for (int j = 0; j < MDIM / 2 / 256; j++) {
        int idx = threadIdx.x + j * 256;
        float2 v = xr2[idx];
        dst[idx] = packh(v.x, v.y);
    }
    __syncthreads();
    if (threadIdx.x == 0) {
        float mx = lg[0]; int mi = 0;
        #pragma unroll
        for (int e = 1; e < EEXP; e++) if (lg[e] > mx) { mx = lg[e]; mi = e; }
        float se = 0.f;
        #pragma unroll
        for (int e = 0; e < EEXP; e++) se += expf(lg[e] - mx);
        g_idx[s] = mi;
        g_gw[s]  = 1.f / se;
    }
}

// ----------------- routing: parallel 3-phase (order-preserving) -------------
#define NCHUNK (S_TOK / 32)   // 256 chunks of 32 tokens
__global__ __launch_bounds__(1024) void route_kernel() {
    __shared__ int cnt[NCHUNK * EEXP];
    int tid = threadIdx.x, w = tid >> 5, lane = tid & 31;

    // Phase A: per-chunk expert counts (warp w owns chunks w*8 .. w*8+7, in order)
    int ids[8];
    #pragma unroll
    for (int i = 0; i < 8; i++) {
        int c = w * 8 + i;
        ids[i] = g_idx[c * 32 + lane];
        #pragma unroll
        for (int e = 0; e < EEXP; e++) {
            unsigned b = __ballot_sync(0xffffffffu, ids[i] == e);
            if (lane == e) cnt[c * EEXP + e] = __popc(b);
        }
    }
    __syncthreads();

    // Phase B: exclusive scan over chunks, one thread per expert
    if (tid < EEXP) {
        int running = 0;
        for (int c = 0; c < NCHUNK; c++) {
            int v = cnt[c * EEXP + tid];
            cnt[c * EEXP + tid] = running;
            running += v;
        }
        g_rows[tid] = min(running, CAP);
    }
    __syncthreads();

    // Phase C: final positions
    #pragma unroll
    for (int i = 0; i < 8; i++) {
        int c = w * 8 + i;
        int id = ids[i];
        int pos = 0;
        #pragma unroll
        for (int e = 0; e < EEXP; e++) {
            unsigned b = __ballot_sync(0xffffffffu, id == e);
            if (id == e) pos = cnt[c * EEXP + e] + __popc(b & ((1u << lane) - 1u));
        }
        int s = c * 32 + lane;
        if (pos < CAP) g_tfs[id * CAP + pos] = s;
        else           g_gw[s] = 0.f;
    }
}

// ----------------- weight transpose (fp16, 64x64 tiles, wide writes) --------
template<bool W1SEL>
__global__ __launch_bounds__(256)
void transpose_split(const float* __restrict__ src) {
    constexpr int R  = W1SEL ? MDIM : HDIM;   // src rows (= out cols = K)
    constexpr int Cc = W1SEL ? HDIM : MDIM;   // src cols (= out rows = N)
    __half* dhi = W1SEL ? g_w1t_hi : g_w2t_hi;
    __shared__ float t[64][65];
    int e = blockIdx.z;
    const float* s = src + (size_t)e * R * Cc;
    size_t ob = (size_t)e * R * Cc;
    int c0 = blockIdx.x * 64, r0 = blockIdx.y * 64;
    int tid = threadIdx.x;
    int rr = tid >> 6, cc = tid & 63;
    #pragma unroll
    for (int i = 0; i < 16; i++) {
        int r = i * 4 + rr;
        t[r][cc] = s[(size_t)(r0 + r) * Cc + c0 + cc];
    }
    __syncthreads();
    int orr = tid >> 5, j = tid & 31;
    #pragma unroll
    for (int i = 0; i < 8; i++) {
        int oc = orr + i * 8;   // src-col index within tile (= out row offset)
        __half2 v = __floats2half2_rn(t[2 * j][oc], t[2 * j + 1][oc]);
        *(__half2*)(dhi + ob + (size_t)(c0 + oc) * R + r0 + 2 * j) = v;
    }
}

// ----------------- HMMA fp16 GEMM (BM=BN=128, 3 stages, 2 CTA/SM) -----------
#define BM 128
#define BN 128
#define BK 64
#define OFF_AHI 0
#define OFF_BHI 16384
#define STG 32768
#define SMEM_BYTES (3 * STG + 1024)

template<bool G1>
__global__ __launch_bounds__(256, 2)
void hgemm(float* __restrict__ outp) {
    constexpr int KD  = G1 ? MDIM : HDIM;
    constexpr int NT  = G1 ? HDIM : MDIM;
    constexpr int KCH = KD / BK;

    int e = blockIdx.z;
    int rows = g_rows[e];
    int rowBase = blockIdx.y * BM;
    if (rowBase >= rows) return;
    int colBase = blockIdx.x * BN;

    extern __shared__ char dsm[];
    uint32_t base = (smem_u32(dsm) + 1023u) & ~1023u;

    int t = threadIdx.x;

    // ---- loader setup: thread t loads 64B half of row (t>>1) ----
    int lr = t >> 1, half = t & 1;
    const __half* aHi;
    if (G1) {
        int rr = rowBase + lr;
        if (rr >= rows) rr = rows - 1;
        int tok = g_tfs[e * CAP + rr];
        aHi = g_x_hi + (size_t)tok * MDIM + half * 32;
    } else {
        aHi = g_h_hi + ((size_t)e * CAP + rowBase + lr) * HDIM + half * 32;
    }
    size_t bo0 = ((size_t)e * NT + colBase + lr) * KD + half * 32;
    const __half* bHi = G1 ? g_w1t_hi : g_w2t_hi;

    uint32_t d0[4];
    #pragma unroll
    for (int i = 0; i < 4; i++)
        d0[i] = SWZ(lr * 128 + (half * 4 + i) * 16);

    auto loadStage = [&](int s, int kt) {
        uint32_t sb = base + s * STG;
        int ko = kt * BK;
        #pragma unroll
        for (int i = 0; i < 4; i++) {
            cpa(sb + OFF_AHI + d0[i], aHi + ko + i * 8);
            cpa(sb + OFF_BHI + d0[i], bHi + bo0 + ko + i * 8);
        }
    };

    // ---- compute setup: 8 warps as 4(m) x 2(n); warp tile 32 x 64 ----
    int wid = t >> 5, lane = t & 31;
    int m0 = (wid >> 1) * 32, n0 = (wid & 1) * 64;
    uint32_t aOff[2];
    #pragma unroll
    for (int mt = 0; mt < 2; mt++)
        aOff[mt] = (m0 + mt * 16 + (lane & 15)) * 128 + ((lane >> 4) * 16);
    uint32_t bOff = (n0 + (lane & 7) + ((lane >> 4) << 3)) * 128 + (((lane >> 3) & 1) * 16);

    float acc[64];
    #pragma unroll
    for (int i = 0; i < 64; i++) acc[i] = 0.f;

    loadStage(0, 0); asm volatile("cp.async.commit_group;" ::: "memory");
    loadStage(1, 1); asm volatile("cp.async.commit_group;" ::: "memory");

    int sIdx = 0;
    for (int kt = 0; kt < KCH; kt++) {
        asm volatile("cp.async.wait_group 1;" ::: "memory");
        __syncthreads();
        if (kt + 2 < KCH) {
            int ns = sIdx + 2; if (ns >= 3) ns -= 3;
            loadStage(ns, kt + 2);
        }
        asm volatile("cp.async.commit_group;" ::: "memory");

        uint32_t sb = base + sIdx * STG;
        #pragma unroll
        for (int ks = 0; ks < 4; ks++) {
            uint32_t ah[2][4];
            #pragma unroll
            for (int mt = 0; mt < 2; mt++)
                ldsm4(ah[mt], sb + OFF_AHI + SWZ(aOff[mt] + ks * 32));
            #pragma unroll
            for (int p = 0; p < 4; p++) {
                uint32_t bh[4];
                ldsm4(bh, sb + OFF_BHI + SWZ(bOff + p * 2048 + ks * 32));
                #pragma unroll
                for (int mt = 0; mt < 2; mt++) {
                    float* c0 = &acc[(mt * 8 + 2 * p) * 4];
                    float* c1 = &acc[(mt * 8 + 2 * p + 1) * 4];
                    mmah(c0, ah[mt], bh[0], bh[1]);
                    mmah(c1, ah[mt], bh[2], bh[3]);
                }
            }
        }
        if (++sIdx == 3) sIdx = 0;
    }

    // ---- epilogue ----
    int rq = lane >> 2, cq = (lane & 3) * 2;
    #pragma unroll
    for (int mt = 0; mt < 2; mt++) {
        #pragma unroll
        for (int h = 0; h < 2; h++) {
            int r = rowBase + m0 + mt * 16 + rq + h * 8;
            if (r < rows) {
                if (G1) {
                    size_t ro = ((size_t)e * CAP + r) * HDIM + colBase + n0 + cq;
                    #pragma unroll
                    for (int nt = 0; nt < 8; nt++) {
                        float v0 = gelu_tanh(acc[(mt * 8 + nt) * 4 + h * 2]);
                        float v1 = gelu_tanh(acc[(mt * 8 + nt) * 4 + h * 2 + 1]);
                        *(uint32_t*)(g_h_hi + ro + nt * 8) = packh(v0, v1);
                    }
                } else {
                    int tok = g_tfs[e * CAP + r];
                    float gw = g_gw[tok];
                    float* dst = outp + (size_t)tok * MDIM + colBase + n0 + cq;
                    #pragma unroll
                    for (int nt = 0; nt < 8; nt++) {
                        float2 v;
                        v.x = acc[(mt * 8 + nt) * 4 + h * 2]     * gw;
                        v.y = acc[(mt * 8 + nt) * 4 + h * 2 + 1] * gw;
                        *(float2*)(dst + nt * 8) = v;
                    }
                }
            }
        }
    }
}

// ----------------- launch ---------------------------------------------------
extern "C" void kernel_launch(void* const* d_in, const int* in_sizes, int n_in,
                              void* d_out, int out_size) {
    const float* x  = (const float*)d_in[0];
    const float* Wg = (const float*)d_in[1];
    const float* W1 = (const float*)d_in[2];
    const float* W2 = (const float*)d_in[3];
    float* out = (float*)d_out;

    static cudaStream_t s2 = nullptr, s3 = nullptr;
    static cudaEvent_t evRoot = nullptr, evW1 = nullptr, evW2 = nullptr;
    if (s2 == nullptr) {
        cudaStreamCreateWithFlags(&s2, cudaStreamNonBlocking);
        cudaStreamCreateWithFlags(&s3, cudaStreamNonBlocking);
        cudaEventCreateWithFlags(&evRoot, cudaEventDisableTiming);
        cudaEventCreateWithFlags(&evW1,   cudaEventDisableTiming);
        cudaEventCreateWithFlags(&evW2,   cudaEventDisableTiming);
        cudaFuncSetAttribute(hgemm<true>,  cudaFuncAttributeMaxDynamicSharedMemorySize, SMEM_BYTES);
        cudaFuncSetAttribute(hgemm<false>, cudaFuncAttributeMaxDynamicSharedMemorySize, SMEM_BYTES);
    }

    // fork two aux branches off the main (captured) stream
    cudaEventRecord(evRoot, 0);
    cudaStreamWaitEvent(s2, evRoot, 0);
    cudaStreamWaitEvent(s3, evRoot, 0);

    // branch s2: W1 transpose (overlaps gate+route on main)
    transpose_split<true ><<<dim3(HDIM / 64, MDIM / 64, EEXP), 256, 0, s2>>>(W1);
    cudaEventRecord(evW1, s2);

    // branch s3: W2 transpose + output clear (overlaps gate/route AND GEMM1)
    transpose_split<false><<<dim3(MDIM / 64, HDIM / 64, EEXP), 256, 0, s3>>>(W2);
    cudaMemsetAsync(d_out, 0, (size_t)S_TOK * MDIM * sizeof(float), s3);
    cudaEventRecord(evW2, s3);

    // main: gate -> route -> (join W1) -> GEMM1 -> (join W2/memset) -> GEMM2
    gate_kernel<<<S_TOK, 256>>>(x, Wg);
    route_kernel<<<1, 1024>>>();
    cudaStreamWaitEvent(0, evW1, 0);
    hgemm<true ><<<dim3(HDIM / BN, CAP / BM, EEXP), 256, SMEM_BYTES>>>(nullptr);
    cudaStreamWaitEvent(0, evW2, 0);
    hgemm<false><<<dim3(MDIM / BN, CAP / BM, EEXP), 256, SMEM_BYTES>>>(out);
}